// round 1
// baseline (speedup 1.0000x reference)
#include <cuda_runtime.h>
#include <math.h>

#define NEXP 32
#define KSEL 4
#define CAP  1280
#define NTOK 8192
#define DDIM 1024
#define IDIM 512

#define TM 64
#define TN 64
#define KB 32
#define PAD 4

// ---- scratch (device globals; no allocations allowed) ----
__device__ int   g_counts[NEXP];
__device__ int   g_row_token[NEXP * CAP];
__device__ int   g_tok_exp[NTOK * KSEL];
__device__ int   g_tok_pos[NTOK * KSEL];
__device__ float g_tok_w[NTOK * KSEL];
__device__ float g_H[(size_t)NEXP * CAP * IDIM];   // 84 MB
__device__ float g_Y[(size_t)NEXP * CAP * DDIM];   // 168 MB

__global__ void zero_counts_kernel() {
    if (threadIdx.x < NEXP) g_counts[threadIdx.x] = 0;
}

// One block (128 threads) per token: logits, top-4, renorm weights, dispatch.
__global__ void router_kernel(const float* __restrict__ x,
                              const float* __restrict__ rw,
                              float* __restrict__ logits_out) {
    __shared__ float xs[DDIM];
    __shared__ float lsh[NEXP];
    const int t = blockIdx.x;
    const int tid = threadIdx.x;

    // load token row into smem
    const float4* xrow = (const float4*)(x + (size_t)t * DDIM);
    float4* xs4 = (float4*)xs;
    for (int i = tid; i < DDIM / 4; i += 128) xs4[i] = xrow[i];
    __syncthreads();

    // 4 threads per expert, each over a 256-wide chunk
    const int e = tid >> 2;
    const int s = tid & 3;
    const float4* w4 = (const float4*)(rw + e * DDIM + s * 256);
    const float4* a4 = (const float4*)(xs + s * 256);
    float acc = 0.f;
#pragma unroll 16
    for (int j = 0; j < 64; j++) {
        float4 a = a4[j], b = w4[j];
        acc += a.x * b.x + a.y * b.y + a.z * b.z + a.w * b.w;
    }
    acc += __shfl_xor_sync(0xffffffffu, acc, 1);
    acc += __shfl_xor_sync(0xffffffffu, acc, 2);
    if (s == 0) lsh[e] = acc;
    __syncthreads();

    if (tid < 32) {
        float lv = lsh[tid];
        if (logits_out) logits_out[(size_t)t * NEXP + tid] = lv;

        // top-4 with lower-index tie-break (matches lax.top_k)
        float cur = lv;
        float selv[KSEL];
        int   seli[KSEL];
#pragma unroll
        for (int k = 0; k < KSEL; k++) {
            float v = cur;
            int idx = tid;
#pragma unroll
            for (int off = 16; off; off >>= 1) {
                float ov = __shfl_xor_sync(0xffffffffu, v, off);
                int   oi = __shfl_xor_sync(0xffffffffu, idx, off);
                if (ov > v || (ov == v && oi < idx)) { v = ov; idx = oi; }
            }
            selv[k] = v;
            seli[k] = idx;
            if (tid == idx) cur = -3.4e38f;
        }

        if (tid < KSEL) {
            // renormalized weights: softmax denominator cancels
            float m = selv[0];
            float sum = 0.f;
#pragma unroll
            for (int k = 0; k < KSEL; k++) sum += expf(selv[k] - m);
            float w = expf(selv[tid] - m) / sum;
            int   ex = seli[tid];
            int p = atomicAdd(&g_counts[ex], 1);
            int o = t * KSEL + tid;
            g_tok_exp[o] = ex;
            g_tok_pos[o] = p;
            g_tok_w[o]   = w;
            if (p < CAP) g_row_token[ex * CAP + p] = t;
        }
    }
}

// Phase 1: H[e, m, i] = silu(X Gw^T) * (X Uw^T), gather token rows directly.
__global__ __launch_bounds__(256, 2)
void phase1_kernel(const float* __restrict__ x,
                   const float* __restrict__ gate_w,
                   const float* __restrict__ up_w) {
    const int e = blockIdx.z;
    const int cnt = min(g_counts[e], CAP);
    const int m0 = blockIdx.y * TM;
    if (m0 >= cnt) return;
    const int i0 = blockIdx.x * TN;

    __shared__ float Xs[KB][TM + PAD];
    __shared__ float Gs[KB][TN + PAD];
    __shared__ float Us[KB][TN + PAD];

    const int tid = threadIdx.x;
    const int tx = tid & 15;
    const int ty = tid >> 4;

    // loader mapping: 64 rows x 8 float4 (=32 k) per tile, 2 passes
    const int lrow = tid >> 2;
    const int lk   = tid & 3;

    const int mrow = m0 + lrow;
    const int tok  = (mrow < cnt) ? g_row_token[e * CAP + mrow] : -1;
    const float* xbase = (tok >= 0) ? (x + (size_t)tok * DDIM) : x;
    const float* gbase = gate_w + ((size_t)e * IDIM + (i0 + lrow)) * DDIM;
    const float* ubase = up_w   + ((size_t)e * IDIM + (i0 + lrow)) * DDIM;

    float accg[4][4] = {};
    float accu[4][4] = {};

    for (int kk = 0; kk < DDIM; kk += KB) {
#pragma unroll
        for (int p = 0; p < 2; p++) {
            int k4 = lk + p * 4;          // float4 index 0..7 within KB
            int kb = k4 * 4;
            float4 vx = make_float4(0.f, 0.f, 0.f, 0.f);
            if (tok >= 0) vx = *(const float4*)(xbase + kk + kb);
            Xs[kb + 0][lrow] = vx.x; Xs[kb + 1][lrow] = vx.y;
            Xs[kb + 2][lrow] = vx.z; Xs[kb + 3][lrow] = vx.w;
            float4 vg = *(const float4*)(gbase + kk + kb);
            Gs[kb + 0][lrow] = vg.x; Gs[kb + 1][lrow] = vg.y;
            Gs[kb + 2][lrow] = vg.z; Gs[kb + 3][lrow] = vg.w;
            float4 vu = *(const float4*)(ubase + kk + kb);
            Us[kb + 0][lrow] = vu.x; Us[kb + 1][lrow] = vu.y;
            Us[kb + 2][lrow] = vu.z; Us[kb + 3][lrow] = vu.w;
        }
        __syncthreads();
#pragma unroll
        for (int k = 0; k < KB; k++) {
            float4 a  = *(const float4*)&Xs[k][ty * 4];
            float4 bg = *(const float4*)&Gs[k][tx * 4];
            float4 bu = *(const float4*)&Us[k][tx * 4];
            float av[4] = {a.x, a.y, a.z, a.w};
            float gv[4] = {bg.x, bg.y, bg.z, bg.w};
            float uv[4] = {bu.x, bu.y, bu.z, bu.w};
#pragma unroll
            for (int i = 0; i < 4; i++)
#pragma unroll
                for (int j = 0; j < 4; j++) {
                    accg[i][j] += av[i] * gv[j];
                    accu[i][j] += av[i] * uv[j];
                }
        }
        __syncthreads();
    }

#pragma unroll
    for (int i = 0; i < 4; i++) {
        int m = m0 + ty * 4 + i;
        if (m < cnt) {
            float4 h;
            float* hp = &h.x;
#pragma unroll
            for (int j = 0; j < 4; j++) {
                float g = accg[i][j], u = accu[i][j];
                hp[j] = g * (1.f / (1.f + expf(-g))) * u;
            }
            *(float4*)&g_H[((size_t)e * CAP + m) * IDIM + i0 + tx * 4] = h;
        }
    }
}

// Phase 2: Y[e, m, d] = H[e, m, :] . down_w[e, d, :]
__global__ __launch_bounds__(256, 2)
void phase2_kernel(const float* __restrict__ down_w) {
    const int e = blockIdx.z;
    const int cnt = min(g_counts[e], CAP);
    const int m0 = blockIdx.y * TM;
    if (m0 >= cnt) return;
    const int d0 = blockIdx.x * TN;

    __shared__ float Hs[KB][TM + PAD];
    __shared__ float Ds[KB][TN + PAD];

    const int tid = threadIdx.x;
    const int tx = tid & 15;
    const int ty = tid >> 4;
    const int lrow = tid >> 2;
    const int lk   = tid & 3;

    const float* hbase = g_H + ((size_t)e * CAP + (m0 + lrow)) * IDIM;
    const float* dbase = down_w + ((size_t)e * DDIM + (d0 + lrow)) * IDIM;

    float acc[4][4] = {};

    for (int kk = 0; kk < IDIM; kk += KB) {
#pragma unroll
        for (int p = 0; p < 2; p++) {
            int k4 = lk + p * 4;
            int kb = k4 * 4;
            float4 vh = *(const float4*)(hbase + kk + kb);
            Hs[kb + 0][lrow] = vh.x; Hs[kb + 1][lrow] = vh.y;
            Hs[kb + 2][lrow] = vh.z; Hs[kb + 3][lrow] = vh.w;
            float4 vd = *(const float4*)(dbase + kk + kb);
            Ds[kb + 0][lrow] = vd.x; Ds[kb + 1][lrow] = vd.y;
            Ds[kb + 2][lrow] = vd.z; Ds[kb + 3][lrow] = vd.w;
        }
        __syncthreads();
#pragma unroll
        for (int k = 0; k < KB; k++) {
            float4 a = *(const float4*)&Hs[k][ty * 4];
            float4 b = *(const float4*)&Ds[k][tx * 4];
            float av[4] = {a.x, a.y, a.z, a.w};
            float bv[4] = {b.x, b.y, b.z, b.w};
#pragma unroll
            for (int i = 0; i < 4; i++)
#pragma unroll
                for (int j = 0; j < 4; j++) acc[i][j] += av[i] * bv[j];
        }
        __syncthreads();
    }

#pragma unroll
    for (int i = 0; i < 4; i++) {
        int m = m0 + ty * 4 + i;
        if (m < cnt) {
            float4 v = make_float4(acc[i][0], acc[i][1], acc[i][2], acc[i][3]);
            *(float4*)&g_Y[((size_t)e * CAP + m) * DDIM + d0 + tx * 4] = v;
        }
    }
}

// Combine: out[t, :] = sum_k w_k * Y[e_k, p_k, :]  (gather, deterministic)
__global__ void combine_kernel(float* __restrict__ out) {
    const int t = blockIdx.x;
    const int d = threadIdx.x * 4;
    float4 acc = make_float4(0.f, 0.f, 0.f, 0.f);
#pragma unroll
    for (int k = 0; k < KSEL; k++) {
        int o = t * KSEL + k;
        int e = g_tok_exp[o];
        int p = g_tok_pos[o];
        float w = g_tok_w[o];
        if (p < CAP) {
            float4 v = *(const float4*)&g_Y[((size_t)e * CAP + p) * DDIM + d];
            acc.x += w * v.x; acc.y += w * v.y;
            acc.z += w * v.z; acc.w += w * v.w;
        }
    }
    *(float4*)&out[(size_t)t * DDIM + d] = acc;
}

extern "C" void kernel_launch(void* const* d_in, const int* in_sizes, int n_in,
                              void* d_out, int out_size) {
    const float* x  = (const float*)d_in[0];
    const float* rw = (const float*)d_in[1];
    const float* gw = (const float*)d_in[2];
    const float* uw = (const float*)d_in[3];
    const float* dw = (const float*)d_in[4];
    float* out = (float*)d_out;
    float* logits = (out_size >= NTOK * DDIM + NTOK * NEXP) ? (out + (size_t)NTOK * DDIM)
                                                            : nullptr;

    zero_counts_kernel<<<1, 32>>>();
    router_kernel<<<NTOK, 128>>>(x, rw, logits);
    phase1_kernel<<<dim3(IDIM / TN, CAP / TM, NEXP), 256>>>(x, gw, uw);
    phase2_kernel<<<dim3(DDIM / TN, CAP / TM, NEXP), 256>>>(dw);
    combine_kernel<<<NTOK, 256>>>(out);
}

// round 5
// speedup vs baseline: 2.3562x; 2.3562x over previous
#include <cuda_runtime.h>
#include <cuda_bf16.h>
#include <math.h>
#include <stdint.h>

#define NEXP 32
#define KSEL 4
#define CAP  1280
#define NTOK 8192
#define DDIM 1024
#define IDIM 512

#define THREADS 256
#define SMEM_GEMM (131072 + 1024)   // 2 x 64KB buffers + token list

// ---------------- scratch (device globals; no allocation allowed) ----------
__device__ int   g_counts[NEXP];
__device__ int   g_row_token[NEXP * CAP];
__device__ int   g_tok_exp[NTOK * KSEL];
__device__ int   g_tok_pos[NTOK * KSEL];
__device__ float g_tok_w[NTOK * KSEL];

__device__ __nv_bfloat16 g_Xhi[(size_t)NTOK * DDIM];
__device__ __nv_bfloat16 g_Xlo[(size_t)NTOK * DDIM];
__device__ __nv_bfloat16 g_GUhi[(size_t)NEXP * 1024 * DDIM];  // gate/up row-interleaved
__device__ __nv_bfloat16 g_GUlo[(size_t)NEXP * 1024 * DDIM];
__device__ __nv_bfloat16 g_Dhi[(size_t)NEXP * DDIM * IDIM];
__device__ __nv_bfloat16 g_Dlo[(size_t)NEXP * DDIM * IDIM];
__device__ __nv_bfloat16 g_Hhi[(size_t)NEXP * CAP * IDIM];
__device__ __nv_bfloat16 g_Hlo[(size_t)NEXP * CAP * IDIM];
__device__ float g_Y[(size_t)NEXP * CAP * DDIM];

// ---------------- PTX helpers (base compute_103 target only) ---------------
__device__ __forceinline__ uint32_t smem_u32(const void* p) {
    uint32_t a;
    asm("{ .reg .u64 t; cvta.to.shared.u64 t, %1; cvt.u32.u64 %0, t; }"
        : "=r"(a) : "l"(p));
    return a;
}
__device__ __forceinline__ void cp_async16(uint32_t dst, const void* src) {
    asm volatile("cp.async.cg.shared.global [%0], [%1], 16;"
                 :: "r"(dst), "l"(src));
}
#define CP_COMMIT() asm volatile("cp.async.commit_group;" ::: "memory")
#define CP_WAIT1()  asm volatile("cp.async.wait_group 1;" ::: "memory")
#define CP_WAIT0()  asm volatile("cp.async.wait_group 0;" ::: "memory")

__device__ __forceinline__ void ldsm4(uint32_t* r, uint32_t a) {
    asm volatile("ldmatrix.sync.aligned.m8n8.x4.shared.b16 {%0,%1,%2,%3}, [%4];"
                 : "=r"(r[0]), "=r"(r[1]), "=r"(r[2]), "=r"(r[3]) : "r"(a));
}
__device__ __forceinline__ void mma_bf16(float* c, const uint32_t* a,
                                         const uint32_t* b) {
    asm volatile(
        "mma.sync.aligned.m16n8k16.row.col.f32.bf16.bf16.f32 "
        "{%0,%1,%2,%3}, {%4,%5,%6,%7}, {%8,%9}, {%0,%1,%2,%3};"
        : "+f"(c[0]), "+f"(c[1]), "+f"(c[2]), "+f"(c[3])
        : "r"(a[0]), "r"(a[1]), "r"(a[2]), "r"(a[3]), "r"(b[0]), "r"(b[1]));
}

__device__ __forceinline__ void split2(float a, float b, uint32_t& hi, uint32_t& lo) {
    __nv_bfloat16 ha = __float2bfloat16(a);
    __nv_bfloat16 hb = __float2bfloat16(b);
    __nv_bfloat16 la = __float2bfloat16(a - __bfloat162float(ha));
    __nv_bfloat16 lb = __float2bfloat16(b - __bfloat162float(hb));
    __nv_bfloat162 H = __halves2bfloat162(ha, hb);
    __nv_bfloat162 L = __halves2bfloat162(la, lb);
    hi = *reinterpret_cast<uint32_t*>(&H);
    lo = *reinterpret_cast<uint32_t*>(&L);
}

// ---------------- prep: fp32 -> split bf16 ----------------------------------
__global__ void split_x_kernel(const float* __restrict__ x) {
    size_t u = (size_t)blockIdx.x * blockDim.x + threadIdx.x;  // 8 floats/unit
    if (u >= (size_t)NTOK * DDIM / 8) return;
    const float4* src = (const float4*)x + u * 2;
    float4 v0 = src[0], v1 = src[1];
    uint32_t h0, l0, h1, l1, h2, l2, h3, l3;
    split2(v0.x, v0.y, h0, l0); split2(v0.z, v0.w, h1, l1);
    split2(v1.x, v1.y, h2, l2); split2(v1.z, v1.w, h3, l3);
    ((uint4*)g_Xhi)[u] = make_uint4(h0, h1, h2, h3);
    ((uint4*)g_Xlo)[u] = make_uint4(l0, l1, l2, l3);
}

// gate/up interleave: GU row r (0..1023 per expert): even -> gate[r>>1], odd -> up[r>>1]
__global__ void split_gu_kernel(const float* __restrict__ gate_w,
                                const float* __restrict__ up_w) {
    size_t u = (size_t)blockIdx.x * blockDim.x + threadIdx.x;
    if (u >= (size_t)NEXP * 1024 * DDIM / 8) return;
    size_t o = u * 8;
    size_t gr = o >> 10;          // global GU row
    int k = (int)(o & 1023);
    int e = (int)(gr >> 10);
    int r = (int)(gr & 1023);
    int i = r >> 1;
    const float* src = ((r & 1) ? up_w : gate_w) + ((size_t)e * IDIM + i) * DDIM + k;
    const float4* s4 = (const float4*)src;
    float4 v0 = s4[0], v1 = s4[1];
    uint32_t h0, l0, h1, l1, h2, l2, h3, l3;
    split2(v0.x, v0.y, h0, l0); split2(v0.z, v0.w, h1, l1);
    split2(v1.x, v1.y, h2, l2); split2(v1.z, v1.w, h3, l3);
    ((uint4*)g_GUhi)[u] = make_uint4(h0, h1, h2, h3);
    ((uint4*)g_GUlo)[u] = make_uint4(l0, l1, l2, l3);
}

__global__ void split_d_kernel(const float* __restrict__ down_w) {
    size_t u = (size_t)blockIdx.x * blockDim.x + threadIdx.x;
    if (u >= (size_t)NEXP * DDIM * IDIM / 8) return;
    const float4* s4 = (const float4*)down_w + u * 2;
    float4 v0 = s4[0], v1 = s4[1];
    uint32_t h0, l0, h1, l1, h2, l2, h3, l3;
    split2(v0.x, v0.y, h0, l0); split2(v0.z, v0.w, h1, l1);
    split2(v1.x, v1.y, h2, l2); split2(v1.z, v1.w, h3, l3);
    ((uint4*)g_Dhi)[u] = make_uint4(h0, h1, h2, h3);
    ((uint4*)g_Dlo)[u] = make_uint4(l0, l1, l2, l3);
}

// ---------------- router / combine ------------------------------------------
__global__ void zero_counts_kernel() {
    if (threadIdx.x < NEXP) g_counts[threadIdx.x] = 0;
}

__global__ void router_kernel(const float* __restrict__ x,
                              const float* __restrict__ rw,
                              float* __restrict__ logits_out) {
    __shared__ float xs[DDIM];
    __shared__ float lsh[NEXP];
    const int t = blockIdx.x;
    const int tid = threadIdx.x;

    const float4* xrow = (const float4*)(x + (size_t)t * DDIM);
    float4* xs4 = (float4*)xs;
    for (int i = tid; i < DDIM / 4; i += 128) xs4[i] = xrow[i];
    __syncthreads();

    const int e = tid >> 2;
    const int s = tid & 3;
    const float4* w4 = (const float4*)(rw + e * DDIM + s * 256);
    const float4* a4 = (const float4*)(xs + s * 256);
    float acc = 0.f;
#pragma unroll 16
    for (int j = 0; j < 64; j++) {
        float4 a = a4[j], b = w4[j];
        acc += a.x * b.x + a.y * b.y + a.z * b.z + a.w * b.w;
    }
    acc += __shfl_xor_sync(0xffffffffu, acc, 1);
    acc += __shfl_xor_sync(0xffffffffu, acc, 2);
    if (s == 0) lsh[e] = acc;
    __syncthreads();

    if (tid < 32) {
        float lv = lsh[tid];
        if (logits_out) logits_out[(size_t)t * NEXP + tid] = lv;

        float cur = lv;
        float selv[KSEL];
        int   seli[KSEL];
#pragma unroll
        for (int k = 0; k < KSEL; k++) {
            float v = cur;
            int idx = tid;
#pragma unroll
            for (int off = 16; off; off >>= 1) {
                float ov = __shfl_xor_sync(0xffffffffu, v, off);
                int   oi = __shfl_xor_sync(0xffffffffu, idx, off);
                if (ov > v || (ov == v && oi < idx)) { v = ov; idx = oi; }
            }
            selv[k] = v;
            seli[k] = idx;
            if (tid == idx) cur = -3.4e38f;
        }

        if (tid < KSEL) {
            float m = selv[0];
            float sum = 0.f;
#pragma unroll
            for (int k = 0; k < KSEL; k++) sum += expf(selv[k] - m);
            float w = expf(selv[tid] - m) / sum;
            int   ex = seli[tid];
            int p = atomicAdd(&g_counts[ex], 1);
            int o = t * KSEL + tid;
            g_tok_exp[o] = ex;
            g_tok_pos[o] = p;
            g_tok_w[o]   = w;
            if (p < CAP) g_row_token[ex * CAP + p] = t;
        }
    }
}

__global__ void combine_kernel(float* __restrict__ out) {
    const int t = blockIdx.x;
    const int d = threadIdx.x * 4;
    float4 acc = make_float4(0.f, 0.f, 0.f, 0.f);
#pragma unroll
    for (int k = 0; k < KSEL; k++) {
        int o = t * KSEL + k;
        int e = g_tok_exp[o];
        int p = g_tok_pos[o];
        float w = g_tok_w[o];
        if (p < CAP) {
            float4 v = *(const float4*)&g_Y[((size_t)e * CAP + p) * DDIM + d];
            acc.x += w * v.x; acc.y += w * v.y;
            acc.z += w * v.z; acc.w += w * v.w;
        }
    }
    *(float4*)&out[(size_t)t * DDIM + d] = acc;
}

// ---------------- GEMM phase 1: H = swiglu(X GU^T), split-bf16 mma.sync ----
// Tiles: M=128 (tokens), N=128 (GU rows, gate/up interleaved), BK=64.
__global__ __launch_bounds__(THREADS, 1)
void phase1_kernel() {
    extern __shared__ char smem[];
    const int e = blockIdx.z;
    const int cnt = min(g_counts[e], CAP);
    const int m0 = blockIdx.y * 128;
    if (m0 >= cnt) return;
    const int x0 = blockIdx.x;          // 64 i-values per tile
    const uint32_t sb = smem_u32(smem);
    int* tok_s = (int*)(smem + 131072);

    const int tid = threadIdx.x;
    const int lane = tid & 31;
    const int wid = tid >> 5;
    const int wm = wid >> 1;
    const int wn = wid & 1;

    if (tid < 128) {
        int m = m0 + tid;
        tok_s[tid] = (m < cnt) ? g_row_token[e * CAP + m] : 0;
    }
    __syncthreads();

    int mytok[4];
#pragma unroll
    for (int it = 0; it < 4; it++) mytok[it] = tok_s[(tid >> 3) + 32 * it];
    const int mycc = tid & 7;

    const size_t bbase = ((size_t)e * 1024 + x0 * 128) * DDIM;

    auto load_chunk = [&](int buf, int c) {
        uint32_t s = sb + buf * 65536;
        int kk = c * 64;
#pragma unroll
        for (int it = 0; it < 4; it++) {
            int row = (tid >> 3) + 32 * it;
            uint32_t dst = s + row * 128 + (((mycc ^ (row & 7))) << 4);
            size_t ka = (size_t)mytok[it] * DDIM + kk + mycc * 8;
            cp_async16(dst,         g_Xhi + ka);
            cp_async16(dst + 16384, g_Xlo + ka);
            size_t kb = bbase + (size_t)row * DDIM + kk + mycc * 8;
            cp_async16(dst + 32768, g_GUhi + kb);
            cp_async16(dst + 49152, g_GUlo + kb);
        }
    };

    float acc[2][8][4] = {};
    const int g = lane >> 3;
    const int ar_off = (lane & 7) + (g & 1) * 8;
    const int ac_off = g >> 1;
    const int br_off = (lane & 7) + (g >> 1) * 8;
    const int bc_off = g & 1;

    load_chunk(0, 0); CP_COMMIT();
    for (int c = 0; c < 16; c++) {
        if (c + 1 < 16) { load_chunk((c + 1) & 1, c + 1); CP_COMMIT(); CP_WAIT1(); }
        else CP_WAIT0();
        __syncthreads();
        uint32_t s = sb + (c & 1) * 65536;
#pragma unroll
        for (int h = 0; h < 4; h++) {
            uint32_t ah[2][4], al[2][4], bh[4][4], bl[4][4];
#pragma unroll
            for (int t = 0; t < 2; t++) {
                int r = wm * 32 + t * 16 + ar_off;
                int cc = h * 2 + ac_off;
                uint32_t a = s + r * 128 + ((cc ^ (r & 7)) << 4);
                ldsm4(ah[t], a);
                ldsm4(al[t], a + 16384);
            }
#pragma unroll
            for (int j2 = 0; j2 < 4; j2++) {
                int n = wn * 64 + j2 * 16 + br_off;
                int cc = h * 2 + bc_off;
                uint32_t a = s + 32768 + n * 128 + ((cc ^ (n & 7)) << 4);
                ldsm4(bh[j2], a);
                ldsm4(bl[j2], a + 16384);
            }
#pragma unroll
            for (int t = 0; t < 2; t++)
#pragma unroll
                for (int j = 0; j < 8; j++)
                    mma_bf16(acc[t][j], ah[t], &bh[j >> 1][(j & 1) * 2]);
#pragma unroll
            for (int t = 0; t < 2; t++)
#pragma unroll
                for (int j = 0; j < 8; j++)
                    mma_bf16(acc[t][j], ah[t], &bl[j >> 1][(j & 1) * 2]);
#pragma unroll
            for (int t = 0; t < 2; t++)
#pragma unroll
                for (int j = 0; j < 8; j++)
                    mma_bf16(acc[t][j], al[t], &bh[j >> 1][(j & 1) * 2]);
        }
        __syncthreads();
    }

    // epilogue: c0 = gate_i, c1 = up_i (row-interleaved B) -> h = silu(g)*u
#pragma unroll
    for (int t = 0; t < 2; t++)
#pragma unroll
        for (int rh = 0; rh < 2; rh++) {
            int m = m0 + wm * 32 + t * 16 + rh * 8 + (lane >> 2);
            if (m < cnt) {
                size_t base = ((size_t)e * CAP + m) * IDIM + x0 * 64 + wn * 32 + (lane & 3);
#pragma unroll
                for (int j = 0; j < 8; j++) {
                    float gg = acc[t][j][rh * 2];
                    float uu = acc[t][j][rh * 2 + 1];
                    float hh = gg * (1.f / (1.f + expf(-gg))) * uu;
                    __nv_bfloat16 bhi = __float2bfloat16(hh);
                    __nv_bfloat16 blo = __float2bfloat16(hh - __bfloat162float(bhi));
                    g_Hhi[base + j * 4] = bhi;
                    g_Hlo[base + j * 4] = blo;
                }
            }
        }
}

// ---------------- GEMM phase 2: Y = H down^T, split-bf16 mma.sync ----------
__global__ __launch_bounds__(THREADS, 1)
void phase2_kernel() {
    extern __shared__ char smem[];
    const int e = blockIdx.z;
    const int cnt = min(g_counts[e], CAP);
    const int m0 = blockIdx.y * 128;
    if (m0 >= cnt) return;
    const int d0 = blockIdx.x * 128;
    const uint32_t sb = smem_u32(smem);

    const int tid = threadIdx.x;
    const int lane = tid & 31;
    const int wid = tid >> 5;
    const int wm = wid >> 1;
    const int wn = wid & 1;
    const int mycc = tid & 7;

    const size_t abase = ((size_t)e * CAP + m0) * IDIM;
    const size_t bbase = ((size_t)e * DDIM + d0) * IDIM;

    auto load_chunk = [&](int buf, int c) {
        uint32_t s = sb + buf * 65536;
        int kk = c * 64;
#pragma unroll
        for (int it = 0; it < 4; it++) {
            int row = (tid >> 3) + 32 * it;
            uint32_t dst = s + row * 128 + (((mycc ^ (row & 7))) << 4);
            size_t ka = abase + (size_t)row * IDIM + kk + mycc * 8;
            cp_async16(dst,         g_Hhi + ka);
            cp_async16(dst + 16384, g_Hlo + ka);
            size_t kb = bbase + (size_t)row * IDIM + kk + mycc * 8;
            cp_async16(dst + 32768, g_Dhi + kb);
            cp_async16(dst + 49152, g_Dlo + kb);
        }
    };

    float acc[2][8][4] = {};
    const int g = lane >> 3;
    const int ar_off = (lane & 7) + (g & 1) * 8;
    const int ac_off = g >> 1;
    const int br_off = (lane & 7) + (g >> 1) * 8;
    const int bc_off = g & 1;

    load_chunk(0, 0); CP_COMMIT();
    for (int c = 0; c < 8; c++) {
        if (c + 1 < 8) { load_chunk((c + 1) & 1, c + 1); CP_COMMIT(); CP_WAIT1(); }
        else CP_WAIT0();
        __syncthreads();
        uint32_t s = sb + (c & 1) * 65536;
#pragma unroll
        for (int h = 0; h < 4; h++) {
            uint32_t ah[2][4], al[2][4], bh[4][4], bl[4][4];
#pragma unroll
            for (int t = 0; t < 2; t++) {
                int r = wm * 32 + t * 16 + ar_off;
                int cc = h * 2 + ac_off;
                uint32_t a = s + r * 128 + ((cc ^ (r & 7)) << 4);
                ldsm4(ah[t], a);
                ldsm4(al[t], a + 16384);
            }
#pragma unroll
            for (int j2 = 0; j2 < 4; j2++) {
                int n = wn * 64 + j2 * 16 + br_off;
                int cc = h * 2 + bc_off;
                uint32_t a = s + 32768 + n * 128 + ((cc ^ (n & 7)) << 4);
                ldsm4(bh[j2], a);
                ldsm4(bl[j2], a + 16384);
            }
#pragma unroll
            for (int t = 0; t < 2; t++)
#pragma unroll
                for (int j = 0; j < 8; j++)
                    mma_bf16(acc[t][j], ah[t], &bh[j >> 1][(j & 1) * 2]);
#pragma unroll
            for (int t = 0; t < 2; t++)
#pragma unroll
                for (int j = 0; j < 8; j++)
                    mma_bf16(acc[t][j], ah[t], &bl[j >> 1][(j & 1) * 2]);
#pragma unroll
            for (int t = 0; t < 2; t++)
#pragma unroll
                for (int j = 0; j < 8; j++)
                    mma_bf16(acc[t][j], al[t], &bh[j >> 1][(j & 1) * 2]);
        }
        __syncthreads();
    }

#pragma unroll
    for (int t = 0; t < 2; t++)
#pragma unroll
        for (int rh = 0; rh < 2; rh++) {
            int m = m0 + wm * 32 + t * 16 + rh * 8 + (lane >> 2);
            if (m < cnt) {
                float* yp = &g_Y[((size_t)e * CAP + m) * DDIM + d0 + wn * 64 + (lane & 3) * 2];
#pragma unroll
                for (int j = 0; j < 8; j++) {
                    float2 v = make_float2(acc[t][j][rh * 2], acc[t][j][rh * 2 + 1]);
                    *(float2*)(yp + j * 8) = v;
                }
            }
        }
}

// ---------------- host ------------------------------------------------------
extern "C" void kernel_launch(void* const* d_in, const int* in_sizes, int n_in,
                              void* d_out, int out_size) {
    const float* x  = (const float*)d_in[0];
    const float* rw = (const float*)d_in[1];
    const float* gw = (const float*)d_in[2];
    const float* uw = (const float*)d_in[3];
    const float* dw = (const float*)d_in[4];
    float* out = (float*)d_out;
    float* logits = (out_size >= NTOK * DDIM + NTOK * NEXP) ? (out + (size_t)NTOK * DDIM)
                                                            : nullptr;

    cudaFuncSetAttribute(phase1_kernel, cudaFuncAttributeMaxDynamicSharedMemorySize, SMEM_GEMM);
    cudaFuncSetAttribute(phase2_kernel, cudaFuncAttributeMaxDynamicSharedMemorySize, SMEM_GEMM);

    zero_counts_kernel<<<1, 32>>>();
    router_kernel<<<NTOK, 128>>>(x, rw, logits);
    split_x_kernel<<<(NTOK * DDIM / 8 + 255) / 256, 256>>>(x);
    split_gu_kernel<<<(NEXP * 1024 * DDIM / 8 + 255) / 256, 256>>>(gw, uw);
    split_d_kernel<<<(NEXP * DDIM * IDIM / 8 + 255) / 256, 256>>>(dw);
    phase1_kernel<<<dim3(IDIM / 64, CAP / 128, NEXP), THREADS, SMEM_GEMM>>>();
    phase2_kernel<<<dim3(DDIM / 128, CAP / 128, NEXP), THREADS, SMEM_GEMM>>>();
    combine_kernel<<<NTOK, 256>>>(out);
}

// round 9
// speedup vs baseline: 2.8089x; 1.1921x over previous
#include <cuda_runtime.h>
#include <cuda_fp16.h>
#include <math.h>
#include <stdint.h>

#define NEXP 32
#define KSEL 4
#define CAP  1280
#define NTOK 8192
#define DDIM 1024
#define IDIM 512

#define THREADS 256
#define TILE_B   16384                 // 128 rows x 64 fp16 (128B)
#define BUF_B    (3 * TILE_B)          // Ahi, Alo, B
#define SMEM_GEMM (2 * BUF_B + 1024)

// ---------------- scratch (device globals; no allocation allowed) ----------
__device__ int   g_counts[NEXP];
__device__ int   g_row_token[NEXP * CAP];
__device__ int   g_tok_exp[NTOK * KSEL];
__device__ int   g_tok_pos[NTOK * KSEL];
__device__ float g_tok_w[NTOK * KSEL];

__device__ __half g_Xhi[(size_t)NTOK * DDIM];
__device__ __half g_Xlo[(size_t)NTOK * DDIM];
__device__ __half g_GU[(size_t)NEXP * 1024 * DDIM];   // gate/up row-interleaved
__device__ __half g_D [(size_t)NEXP * DDIM * IDIM];
__device__ __half g_Hhi[(size_t)NEXP * CAP * IDIM];
__device__ __half g_Hlo[(size_t)NEXP * CAP * IDIM];
__device__ float g_Y[(size_t)NEXP * CAP * DDIM];

// ---------------- PTX helpers (base compute_103 target only) ---------------
__device__ __forceinline__ uint32_t smem_u32(const void* p) {
    uint32_t a;
    asm("{ .reg .u64 t; cvta.to.shared.u64 t, %1; cvt.u32.u64 %0, t; }"
        : "=r"(a) : "l"(p));
    return a;
}
__device__ __forceinline__ void cp_async16(uint32_t dst, const void* src) {
    asm volatile("cp.async.cg.shared.global [%0], [%1], 16;"
                 :: "r"(dst), "l"(src));
}
#define CP_COMMIT() asm volatile("cp.async.commit_group;" ::: "memory")
#define CP_WAIT1()  asm volatile("cp.async.wait_group 1;" ::: "memory")
#define CP_WAIT0()  asm volatile("cp.async.wait_group 0;" ::: "memory")

__device__ __forceinline__ void ldsm4(uint32_t* r, uint32_t a) {
    asm volatile("ldmatrix.sync.aligned.m8n8.x4.shared.b16 {%0,%1,%2,%3}, [%4];"
                 : "=r"(r[0]), "=r"(r[1]), "=r"(r[2]), "=r"(r[3]) : "r"(a));
}
__device__ __forceinline__ void mma_f16(float* c, const uint32_t* a,
                                        const uint32_t* b) {
    asm volatile(
        "mma.sync.aligned.m16n8k16.row.col.f32.f16.f16.f32 "
        "{%0,%1,%2,%3}, {%4,%5,%6,%7}, {%8,%9}, {%0,%1,%2,%3};"
        : "+f"(c[0]), "+f"(c[1]), "+f"(c[2]), "+f"(c[3])
        : "r"(a[0]), "r"(a[1]), "r"(a[2]), "r"(a[3]), "r"(b[0]), "r"(b[1]));
}

__device__ __forceinline__ uint32_t packh2(float a, float b) {
    __half2 h = __floats2half2_rn(a, b);
    return *reinterpret_cast<uint32_t*>(&h);
}
// exact fp16 pair split of two floats
__device__ __forceinline__ void split2h(float a, float b, uint32_t& hi, uint32_t& lo) {
    __half ha = __float2half_rn(a);
    __half hb = __float2half_rn(b);
    float ra = a - __half2float(ha);
    float rb = b - __half2float(hb);
    __half2 H = __halves2half2(ha, hb);
    hi = *reinterpret_cast<uint32_t*>(&H);
    lo = packh2(ra, rb);
}

// ---------------- prep kernels ----------------------------------------------
__global__ void split_x_kernel(const float* __restrict__ x) {
    size_t u = (size_t)blockIdx.x * blockDim.x + threadIdx.x;  // 8 floats/unit
    if (u >= (size_t)NTOK * DDIM / 8) return;
    const float4* src = (const float4*)x + u * 2;
    float4 v0 = src[0], v1 = src[1];
    uint32_t h0, l0, h1, l1, h2, l2, h3, l3;
    split2h(v0.x, v0.y, h0, l0); split2h(v0.z, v0.w, h1, l1);
    split2h(v1.x, v1.y, h2, l2); split2h(v1.z, v1.w, h3, l3);
    ((uint4*)g_Xhi)[u] = make_uint4(h0, h1, h2, h3);
    ((uint4*)g_Xlo)[u] = make_uint4(l0, l1, l2, l3);
}

// gate/up interleave: GU row r (0..1023): even -> gate[r>>1], odd -> up[r>>1]
__global__ void convert_gu_kernel(const float* __restrict__ gate_w,
                                  const float* __restrict__ up_w) {
    size_t u = (size_t)blockIdx.x * blockDim.x + threadIdx.x;
    if (u >= (size_t)NEXP * 1024 * DDIM / 8) return;
    size_t o = u * 8;
    size_t gr = o >> 10;
    int k = (int)(o & 1023);
    int e = (int)(gr >> 10);
    int r = (int)(gr & 1023);
    int i = r >> 1;
    const float* src = ((r & 1) ? up_w : gate_w) + ((size_t)e * IDIM + i) * DDIM + k;
    const float4* s4 = (const float4*)src;
    float4 v0 = s4[0], v1 = s4[1];
    ((uint4*)g_GU)[u] = make_uint4(packh2(v0.x, v0.y), packh2(v0.z, v0.w),
                                   packh2(v1.x, v1.y), packh2(v1.z, v1.w));
}

__global__ void convert_d_kernel(const float* __restrict__ down_w) {
    size_t u = (size_t)blockIdx.x * blockDim.x + threadIdx.x;
    if (u >= (size_t)NEXP * DDIM * IDIM / 8) return;
    const float4* s4 = (const float4*)down_w + u * 2;
    float4 v0 = s4[0], v1 = s4[1];
    ((uint4*)g_D)[u] = make_uint4(packh2(v0.x, v0.y), packh2(v0.z, v0.w),
                                  packh2(v1.x, v1.y), packh2(v1.z, v1.w));
}

// ---------------- router / combine ------------------------------------------
__global__ void zero_counts_kernel() {
    if (threadIdx.x < NEXP) g_counts[threadIdx.x] = 0;
}

__global__ void router_kernel(const float* __restrict__ x,
                              const float* __restrict__ rw,
                              float* __restrict__ logits_out) {
    __shared__ float xs[DDIM];
    __shared__ float lsh[NEXP];
    const int t = blockIdx.x;
    const int tid = threadIdx.x;

    const float4* xrow = (const float4*)(x + (size_t)t * DDIM);
    float4* xs4 = (float4*)xs;
    for (int i = tid; i < DDIM / 4; i += 128) xs4[i] = xrow[i];
    __syncthreads();

    const int e = tid >> 2;
    const int s = tid & 3;
    const float4* w4 = (const float4*)(rw + e * DDIM + s * 256);
    const float4* a4 = (const float4*)(xs + s * 256);
    float acc = 0.f;
#pragma unroll 16
    for (int j = 0; j < 64; j++) {
        float4 a = a4[j], b = w4[j];
        acc += a.x * b.x + a.y * b.y + a.z * b.z + a.w * b.w;
    }
    acc += __shfl_xor_sync(0xffffffffu, acc, 1);
    acc += __shfl_xor_sync(0xffffffffu, acc, 2);
    if (s == 0) lsh[e] = acc;
    __syncthreads();

    if (tid < 32) {
        float lv = lsh[tid];
        if (logits_out) logits_out[(size_t)t * NEXP + tid] = lv;

        float cur = lv;
        float selv[KSEL];
        int   seli[KSEL];
#pragma unroll
        for (int k = 0; k < KSEL; k++) {
            float v = cur;
            int idx = tid;
#pragma unroll
            for (int off = 16; off; off >>= 1) {
                float ov = __shfl_xor_sync(0xffffffffu, v, off);
                int   oi = __shfl_xor_sync(0xffffffffu, idx, off);
                if (ov > v || (ov == v && oi < idx)) { v = ov; idx = oi; }
            }
            selv[k] = v;
            seli[k] = idx;
            if (tid == idx) cur = -3.4e38f;
        }

        if (tid < KSEL) {
            float m = selv[0];
            float sum = 0.f;
#pragma unroll
            for (int k = 0; k < KSEL; k++) sum += expf(selv[k] - m);
            float w = expf(selv[tid] - m) / sum;
            int   ex = seli[tid];
            int p = atomicAdd(&g_counts[ex], 1);
            int o = t * KSEL + tid;
            g_tok_exp[o] = ex;
            g_tok_pos[o] = p;
            g_tok_w[o]   = w;
            if (p < CAP) g_row_token[ex * CAP + p] = t;
        }
    }
}

__global__ void combine_kernel(float* __restrict__ out) {
    const int t = blockIdx.x;
    const int d = threadIdx.x * 4;
    float4 acc = make_float4(0.f, 0.f, 0.f, 0.f);
#pragma unroll
    for (int k = 0; k < KSEL; k++) {
        int o = t * KSEL + k;
        int e = g_tok_exp[o];
        int p = g_tok_pos[o];
        float w = g_tok_w[o];
        if (p < CAP) {
            float4 v = *(const float4*)&g_Y[((size_t)e * CAP + p) * DDIM + d];
            acc.x += w * v.x; acc.y += w * v.y;
            acc.z += w * v.z; acc.w += w * v.w;
        }
    }
    *(float4*)&out[(size_t)t * DDIM + d] = acc;
}

// ---------------- GEMM phase 1: H = swiglu(X GU^T), 2-pass fp16 mma.sync ---
__global__ __launch_bounds__(THREADS, 1)
void phase1_kernel() {
    extern __shared__ char smem[];
    const int e = blockIdx.z;
    const int cnt = min(g_counts[e], CAP);
    const int m0 = blockIdx.y * 128;
    if (m0 >= cnt) return;
    const int x0 = blockIdx.x;          // 64 i-values per tile
    const uint32_t sb = smem_u32(smem);
    int* tok_s = (int*)(smem + 2 * BUF_B);

    const int tid = threadIdx.x;
    const int lane = tid & 31;
    const int wid = tid >> 5;
    const int wm = wid >> 1;
    const int wn = wid & 1;

    if (tid < 128) {
        int m = m0 + tid;
        tok_s[tid] = (m < cnt) ? g_row_token[e * CAP + m] : 0;
    }
    __syncthreads();

    int mytok[4];
#pragma unroll
    for (int it = 0; it < 4; it++) mytok[it] = tok_s[(tid >> 3) + 32 * it];
    const int mycc = tid & 7;

    const size_t bbase = ((size_t)e * 1024 + x0 * 128) * DDIM;

    auto load_chunk = [&](int buf, int c) {
        uint32_t s = sb + buf * BUF_B;
        int kk = c * 64;
#pragma unroll
        for (int it = 0; it < 4; it++) {
            int row = (tid >> 3) + 32 * it;
            uint32_t dst = s + row * 128 + (((mycc ^ (row & 7))) << 4);
            size_t ka = (size_t)mytok[it] * DDIM + kk + mycc * 8;
            cp_async16(dst,              g_Xhi + ka);
            cp_async16(dst + TILE_B,     g_Xlo + ka);
            size_t kb = bbase + (size_t)row * DDIM + kk + mycc * 8;
            cp_async16(dst + 2 * TILE_B, g_GU + kb);
        }
    };

    float acc[2][8][4] = {};
    const int g = lane >> 3;
    const int ar_off = (lane & 7) + (g & 1) * 8;
    const int ac_off = g >> 1;
    const int br_off = (lane & 7) + (g >> 1) * 8;
    const int bc_off = g & 1;

    load_chunk(0, 0); CP_COMMIT();
    for (int c = 0; c < 16; c++) {
        if (c + 1 < 16) { load_chunk((c + 1) & 1, c + 1); CP_COMMIT(); CP_WAIT1(); }
        else CP_WAIT0();
        __syncthreads();
        uint32_t s = sb + (c & 1) * BUF_B;
#pragma unroll
        for (int h = 0; h < 4; h++) {
            uint32_t ah[2][4], al[2][4], bb[4][4];
#pragma unroll
            for (int t = 0; t < 2; t++) {
                int r = wm * 32 + t * 16 + ar_off;
                int cc = h * 2 + ac_off;
                uint32_t a = s + r * 128 + ((cc ^ (r & 7)) << 4);
                ldsm4(ah[t], a);
                ldsm4(al[t], a + TILE_B);
            }
#pragma unroll
            for (int j2 = 0; j2 < 4; j2++) {
                int n = wn * 64 + j2 * 16 + br_off;
                int cc = h * 2 + bc_off;
                ldsm4(bb[j2], s + 2 * TILE_B + n * 128 + ((cc ^ (n & 7)) << 4));
            }
#pragma unroll
            for (int t = 0; t < 2; t++)
#pragma unroll
                for (int j = 0; j < 8; j++)
                    mma_f16(acc[t][j], ah[t], &bb[j >> 1][(j & 1) * 2]);
#pragma unroll
            for (int t = 0; t < 2; t++)
#pragma unroll
                for (int j = 0; j < 8; j++)
                    mma_f16(acc[t][j], al[t], &bb[j >> 1][(j & 1) * 2]);
        }
        __syncthreads();
    }

    // epilogue: c0 = gate_i, c1 = up_i (row-interleaved B) -> h = silu(g)*u
#pragma unroll
    for (int t = 0; t < 2; t++)
#pragma unroll
        for (int rh = 0; rh < 2; rh++) {
            int m = m0 + wm * 32 + t * 16 + rh * 8 + (lane >> 2);
            if (m < cnt) {
                size_t base = ((size_t)e * CAP + m) * IDIM + x0 * 64 + wn * 32 + (lane & 3);
#pragma unroll
                for (int j = 0; j < 8; j++) {
                    float gg = acc[t][j][rh * 2];
                    float uu = acc[t][j][rh * 2 + 1];
                    float hh = gg * (1.f / (1.f + expf(-gg))) * uu;
                    __half bhi = __float2half_rn(hh);
                    __half blo = __float2half_rn(hh - __half2float(bhi));
                    g_Hhi[base + j * 4] = bhi;
                    g_Hlo[base + j * 4] = blo;
                }
            }
        }
}

// ---------------- GEMM phase 2: Y = H down^T, 2-pass fp16 mma.sync ---------
__global__ __launch_bounds__(THREADS, 1)
void phase2_kernel() {
    extern __shared__ char smem[];
    const int e = blockIdx.z;
    const int cnt = min(g_counts[e], CAP);
    const int m0 = blockIdx.y * 128;
    if (m0 >= cnt) return;
    const int d0 = blockIdx.x * 128;
    const uint32_t sb = smem_u32(smem);

    const int tid = threadIdx.x;
    const int lane = tid & 31;
    const int wid = tid >> 5;
    const int wm = wid >> 1;
    const int wn = wid & 1;
    const int mycc = tid & 7;

    const size_t abase = ((size_t)e * CAP + m0) * IDIM;
    const size_t bbase = ((size_t)e * DDIM + d0) * IDIM;

    auto load_chunk = [&](int buf, int c) {
        uint32_t s = sb + buf * BUF_B;
        int kk = c * 64;
#pragma unroll
        for (int it = 0; it < 4; it++) {
            int row = (tid >> 3) + 32 * it;
            uint32_t dst = s + row * 128 + (((mycc ^ (row & 7))) << 4);
            size_t ka = abase + (size_t)row * IDIM + kk + mycc * 8;
            cp_async16(dst,              g_Hhi + ka);
            cp_async16(dst + TILE_B,     g_Hlo + ka);
            size_t kb = bbase + (size_t)row * IDIM + kk + mycc * 8;
            cp_async16(dst + 2 * TILE_B, g_D + kb);
        }
    };

    float acc[2][8][4] = {};
    const int g = lane >> 3;
    const int ar_off = (lane & 7) + (g & 1) * 8;
    const int ac_off = g >> 1;
    const int br_off = (lane & 7) + (g >> 1) * 8;
    const int bc_off = g & 1;

    load_chunk(0, 0); CP_COMMIT();
    for (int c = 0; c < 8; c++) {
        if (c + 1 < 8) { load_chunk((c + 1) & 1, c + 1); CP_COMMIT(); CP_WAIT1(); }
        else CP_WAIT0();
        __syncthreads();
        uint32_t s = sb + (c & 1) * BUF_B;
#pragma unroll
        for (int h = 0; h < 4; h++) {
            uint32_t ah[2][4], al[2][4], bb[4][4];
#pragma unroll
            for (int t = 0; t < 2; t++) {
                int r = wm * 32 + t * 16 + ar_off;
                int cc = h * 2 + ac_off;
                uint32_t a = s + r * 128 + ((cc ^ (r & 7)) << 4);
                ldsm4(ah[t], a);
                ldsm4(al[t], a + TILE_B);
            }
#pragma unroll
            for (int j2 = 0; j2 < 4; j2++) {
                int n = wn * 64 + j2 * 16 + br_off;
                int cc = h * 2 + bc_off;
                ldsm4(bb[j2], s + 2 * TILE_B + n * 128 + ((cc ^ (n & 7)) << 4));
            }
#pragma unroll
            for (int t = 0; t < 2; t++)
#pragma unroll
                for (int j = 0; j < 8; j++)
                    mma_f16(acc[t][j], ah[t], &bb[j >> 1][(j & 1) * 2]);
#pragma unroll
            for (int t = 0; t < 2; t++)
#pragma unroll
                for (int j = 0; j < 8; j++)
                    mma_f16(acc[t][j], al[t], &bb[j >> 1][(j & 1) * 2]);
        }
        __syncthreads();
    }

#pragma unroll
    for (int t = 0; t < 2; t++)
#pragma unroll
        for (int rh = 0; rh < 2; rh++) {
            int m = m0 + wm * 32 + t * 16 + rh * 8 + (lane >> 2);
            if (m < cnt) {
                float* yp = &g_Y[((size_t)e * CAP + m) * DDIM + d0 + wn * 64 + (lane & 3) * 2];
#pragma unroll
                for (int j = 0; j < 8; j++) {
                    float2 v = make_float2(acc[t][j][rh * 2], acc[t][j][rh * 2 + 1]);
                    *(float2*)(yp + j * 8) = v;
                }
            }
        }
}

// ---------------- host ------------------------------------------------------
extern "C" void kernel_launch(void* const* d_in, const int* in_sizes, int n_in,
                              void* d_out, int out_size) {
    const float* x  = (const float*)d_in[0];
    const float* rw = (const float*)d_in[1];
    const float* gw = (const float*)d_in[2];
    const float* uw = (const float*)d_in[3];
    const float* dw = (const float*)d_in[4];
    float* out = (float*)d_out;
    float* logits = (out_size >= NTOK * DDIM + NTOK * NEXP) ? (out + (size_t)NTOK * DDIM)
                                                            : nullptr;

    cudaFuncSetAttribute(phase1_kernel, cudaFuncAttributeMaxDynamicSharedMemorySize, SMEM_GEMM);
    cudaFuncSetAttribute(phase2_kernel, cudaFuncAttributeMaxDynamicSharedMemorySize, SMEM_GEMM);

    zero_counts_kernel<<<1, 32>>>();
    router_kernel<<<NTOK, 128>>>(x, rw, logits);
    split_x_kernel<<<(NTOK * DDIM / 8 + 255) / 256, 256>>>(x);
    convert_gu_kernel<<<(NEXP * 1024 * DDIM / 8 + 255) / 256, 256>>>(gw, uw);
    convert_d_kernel<<<(NEXP * DDIM * IDIM / 8 + 255) / 256, 256>>>(dw);
    phase1_kernel<<<dim3(IDIM / 64, CAP / 128, NEXP), THREADS, SMEM_GEMM>>>();
    phase2_kernel<<<dim3(DDIM / 128, CAP / 128, NEXP), THREADS, SMEM_GEMM>>>();
    combine_kernel<<<NTOK, 256>>>(out);
}

// round 10
// speedup vs baseline: 3.1664x; 1.1273x over previous
#include <cuda_runtime.h>
#include <cuda_fp16.h>
#include <math.h>
#include <stdint.h>

#define NEXP 32
#define KSEL 4
#define CAP  1280
#define NTOK 8192
#define DDIM 1024
#define IDIM 512

#define THREADS 256
#define TILE_B   16384                 // 128 rows x 64 fp16 (128B)
#define SMEM_P1  (2 * 3 * TILE_B + 1024)
#define SMEM_P2  (2 * 2 * TILE_B + 1024)

// ---------------- scratch (device globals; no allocation allowed) ----------
__device__ int   g_counts[NEXP];
__device__ int   g_row_token[NEXP * CAP];
__device__ int   g_tok_exp[NTOK * KSEL];
__device__ int   g_tok_pos[NTOK * KSEL];
__device__ float g_tok_w[NTOK * KSEL];

__device__ __half g_Xhi[(size_t)NTOK * DDIM];
__device__ __half g_Xlo[(size_t)NTOK * DDIM];
__device__ __half g_GU[(size_t)NEXP * 1024 * DDIM];   // gate/up row-interleaved
__device__ __half g_D [(size_t)NEXP * DDIM * IDIM];
__device__ __half g_H [(size_t)NEXP * CAP * IDIM];
__device__ float g_Y[(size_t)NEXP * CAP * DDIM];

// ---------------- PTX helpers (base compute_103 target only) ---------------
__device__ __forceinline__ uint32_t smem_u32(const void* p) {
    uint32_t a;
    asm("{ .reg .u64 t; cvta.to.shared.u64 t, %1; cvt.u32.u64 %0, t; }"
        : "=r"(a) : "l"(p));
    return a;
}
__device__ __forceinline__ void cp_async16(uint32_t dst, const void* src) {
    asm volatile("cp.async.cg.shared.global [%0], [%1], 16;"
                 :: "r"(dst), "l"(src));
}
#define CP_COMMIT() asm volatile("cp.async.commit_group;" ::: "memory")
#define CP_WAIT1()  asm volatile("cp.async.wait_group 1;" ::: "memory")
#define CP_WAIT0()  asm volatile("cp.async.wait_group 0;" ::: "memory")

__device__ __forceinline__ void ldsm4(uint32_t* r, uint32_t a) {
    asm volatile("ldmatrix.sync.aligned.m8n8.x4.shared.b16 {%0,%1,%2,%3}, [%4];"
                 : "=r"(r[0]), "=r"(r[1]), "=r"(r[2]), "=r"(r[3]) : "r"(a));
}
__device__ __forceinline__ void mma_f16(float* c, const uint32_t* a,
                                        const uint32_t* b) {
    asm volatile(
        "mma.sync.aligned.m16n8k16.row.col.f32.f16.f16.f32 "
        "{%0,%1,%2,%3}, {%4,%5,%6,%7}, {%8,%9}, {%0,%1,%2,%3};"
        : "+f"(c[0]), "+f"(c[1]), "+f"(c[2]), "+f"(c[3])
        : "r"(a[0]), "r"(a[1]), "r"(a[2]), "r"(a[3]), "r"(b[0]), "r"(b[1]));
}

__device__ __forceinline__ uint32_t packh2(float a, float b) {
    __half2 h = __floats2half2_rn(a, b);
    return *reinterpret_cast<uint32_t*>(&h);
}
__device__ __forceinline__ void split2h(float a, float b, uint32_t& hi, uint32_t& lo) {
    __half ha = __float2half_rn(a);
    __half hb = __float2half_rn(b);
    float ra = a - __half2float(ha);
    float rb = b - __half2float(hb);
    __half2 H = __halves2half2(ha, hb);
    hi = *reinterpret_cast<uint32_t*>(&H);
    lo = packh2(ra, rb);
}

// ---------------- prep kernels ----------------------------------------------
__global__ void split_x_kernel(const float* __restrict__ x) {
    size_t u = (size_t)blockIdx.x * blockDim.x + threadIdx.x;  // 8 floats/unit
    if (u >= (size_t)NTOK * DDIM / 8) return;
    const float4* src = (const float4*)x + u * 2;
    float4 v0 = src[0], v1 = src[1];
    uint32_t h0, l0, h1, l1, h2, l2, h3, l3;
    split2h(v0.x, v0.y, h0, l0); split2h(v0.z, v0.w, h1, l1);
    split2h(v1.x, v1.y, h2, l2); split2h(v1.z, v1.w, h3, l3);
    ((uint4*)g_Xhi)[u] = make_uint4(h0, h1, h2, h3);
    ((uint4*)g_Xlo)[u] = make_uint4(l0, l1, l2, l3);
}

// gate/up interleave: GU row r (0..1023): even -> gate[r>>1], odd -> up[r>>1]
__global__ void convert_gu_kernel(const float* __restrict__ gate_w,
                                  const float* __restrict__ up_w) {
    size_t u = (size_t)blockIdx.x * blockDim.x + threadIdx.x;
    if (u >= (size_t)NEXP * 1024 * DDIM / 8) return;
    size_t o = u * 8;
    size_t gr = o >> 10;
    int k = (int)(o & 1023);
    int e = (int)(gr >> 10);
    int r = (int)(gr & 1023);
    int i = r >> 1;
    const float* src = ((r & 1) ? up_w : gate_w) + ((size_t)e * IDIM + i) * DDIM + k;
    const float4* s4 = (const float4*)src;
    float4 v0 = s4[0], v1 = s4[1];
    ((uint4*)g_GU)[u] = make_uint4(packh2(v0.x, v0.y), packh2(v0.z, v0.w),
                                   packh2(v1.x, v1.y), packh2(v1.z, v1.w));
}

__global__ void convert_d_kernel(const float* __restrict__ down_w) {
    size_t u = (size_t)blockIdx.x * blockDim.x + threadIdx.x;
    if (u >= (size_t)NEXP * DDIM * IDIM / 8) return;
    const float4* s4 = (const float4*)down_w + u * 2;
    float4 v0 = s4[0], v1 = s4[1];
    ((uint4*)g_D)[u] = make_uint4(packh2(v0.x, v0.y), packh2(v0.z, v0.w),
                                  packh2(v1.x, v1.y), packh2(v1.z, v1.w));
}

// ---------------- router / combine ------------------------------------------
__global__ void zero_counts_kernel() {
    if (threadIdx.x < NEXP) g_counts[threadIdx.x] = 0;
}

__global__ void router_kernel(const float* __restrict__ x,
                              const float* __restrict__ rw,
                              float* __restrict__ logits_out) {
    __shared__ float xs[DDIM];
    __shared__ float lsh[NEXP];
    const int t = blockIdx.x;
    const int tid = threadIdx.x;

    const float4* xrow = (const float4*)(x + (size_t)t * DDIM);
    float4* xs4 = (float4*)xs;
    for (int i = tid; i < DDIM / 4; i += 128) xs4[i] = xrow[i];
    __syncthreads();

    const int e = tid >> 2;
    const int s = tid & 3;
    const float4* w4 = (const float4*)(rw + e * DDIM + s * 256);
    const float4* a4 = (const float4*)(xs + s * 256);
    float acc = 0.f;
#pragma unroll 16
    for (int j = 0; j < 64; j++) {
        float4 a = a4[j], b = w4[j];
        acc += a.x * b.x + a.y * b.y + a.z * b.z + a.w * b.w;
    }
    acc += __shfl_xor_sync(0xffffffffu, acc, 1);
    acc += __shfl_xor_sync(0xffffffffu, acc, 2);
    if (s == 0) lsh[e] = acc;
    __syncthreads();

    if (tid < 32) {
        float lv = lsh[tid];
        if (logits_out) logits_out[(size_t)t * NEXP + tid] = lv;

        float cur = lv;
        float selv[KSEL];
        int   seli[KSEL];
#pragma unroll
        for (int k = 0; k < KSEL; k++) {
            float v = cur;
            int idx = tid;
#pragma unroll
            for (int off = 16; off; off >>= 1) {
                float ov = __shfl_xor_sync(0xffffffffu, v, off);
                int   oi = __shfl_xor_sync(0xffffffffu, idx, off);
                if (ov > v || (ov == v && oi < idx)) { v = ov; idx = oi; }
            }
            selv[k] = v;
            seli[k] = idx;
            if (tid == idx) cur = -3.4e38f;
        }

        if (tid < KSEL) {
            float m = selv[0];
            float sum = 0.f;
#pragma unroll
            for (int k = 0; k < KSEL; k++) sum += expf(selv[k] - m);
            float w = expf(selv[tid] - m) / sum;
            int   ex = seli[tid];
            int p = atomicAdd(&g_counts[ex], 1);
            int o = t * KSEL + tid;
            g_tok_exp[o] = ex;
            g_tok_pos[o] = p;
            g_tok_w[o]   = w;
            if (p < CAP) g_row_token[ex * CAP + p] = t;
        }
    }
}

__global__ void combine_kernel(float* __restrict__ out) {
    const int t = blockIdx.x;
    const int d = threadIdx.x * 4;
    float4 acc = make_float4(0.f, 0.f, 0.f, 0.f);
#pragma unroll
    for (int k = 0; k < KSEL; k++) {
        int o = t * KSEL + k;
        int e = g_tok_exp[o];
        int p = g_tok_pos[o];
        float w = g_tok_w[o];
        if (p < CAP) {
            float4 v = *(const float4*)&g_Y[((size_t)e * CAP + p) * DDIM + d];
            acc.x += w * v.x; acc.y += w * v.y;
            acc.z += w * v.z; acc.w += w * v.w;
        }
    }
    *(float4*)&out[(size_t)t * DDIM + d] = acc;
}

// ---------------- GEMM phase 1: H = swiglu(X GU^T), 2-pass fp16 mma.sync ---
__global__ __launch_bounds__(THREADS, 1)
void phase1_kernel() {
    extern __shared__ char smem[];
    const int e = blockIdx.z;
    const int cnt = min(g_counts[e], CAP);
    const int m0 = blockIdx.y * 128;
    if (m0 >= cnt) return;
    const int x0 = blockIdx.x;          // 64 i-values per tile
    const uint32_t sb = smem_u32(smem);
    int* tok_s = (int*)(smem + 2 * 3 * TILE_B);

    const int tid = threadIdx.x;
    const int lane = tid & 31;
    const int wid = tid >> 5;
    const int wm = wid >> 1;
    const int wn = wid & 1;

    if (tid < 128) {
        int m = m0 + tid;
        tok_s[tid] = (m < cnt) ? g_row_token[e * CAP + m] : 0;
    }
    __syncthreads();

    int mytok[4];
#pragma unroll
    for (int it = 0; it < 4; it++) mytok[it] = tok_s[(tid >> 3) + 32 * it];
    const int mycc = tid & 7;

    const size_t bbase = ((size_t)e * 1024 + x0 * 128) * DDIM;

    auto load_chunk = [&](int buf, int c) {
        uint32_t s = sb + buf * 3 * TILE_B;
        int kk = c * 64;
#pragma unroll
        for (int it = 0; it < 4; it++) {
            int row = (tid >> 3) + 32 * it;
            uint32_t dst = s + row * 128 + (((mycc ^ (row & 7))) << 4);
            size_t ka = (size_t)mytok[it] * DDIM + kk + mycc * 8;
            cp_async16(dst,              g_Xhi + ka);
            cp_async16(dst + TILE_B,     g_Xlo + ka);
            size_t kb = bbase + (size_t)row * DDIM + kk + mycc * 8;
            cp_async16(dst + 2 * TILE_B, g_GU + kb);
        }
    };

    float acc[2][8][4] = {};
    const int g = lane >> 3;
    const int ar_off = (lane & 7) + (g & 1) * 8;
    const int ac_off = g >> 1;
    const int br_off = (lane & 7) + (g >> 1) * 8;
    const int bc_off = g & 1;

    load_chunk(0, 0); CP_COMMIT();
    for (int c = 0; c < 16; c++) {
        if (c + 1 < 16) { load_chunk((c + 1) & 1, c + 1); CP_COMMIT(); CP_WAIT1(); }
        else CP_WAIT0();
        __syncthreads();
        uint32_t s = sb + (c & 1) * 3 * TILE_B;
#pragma unroll
        for (int h = 0; h < 4; h++) {
            uint32_t ah[2][4], al[2][4], bb[4][4];
#pragma unroll
            for (int t = 0; t < 2; t++) {
                int r = wm * 32 + t * 16 + ar_off;
                int cc = h * 2 + ac_off;
                uint32_t a = s + r * 128 + ((cc ^ (r & 7)) << 4);
                ldsm4(ah[t], a);
                ldsm4(al[t], a + TILE_B);
            }
#pragma unroll
            for (int j2 = 0; j2 < 4; j2++) {
                int n = wn * 64 + j2 * 16 + br_off;
                int cc = h * 2 + bc_off;
                ldsm4(bb[j2], s + 2 * TILE_B + n * 128 + ((cc ^ (n & 7)) << 4));
            }
#pragma unroll
            for (int t = 0; t < 2; t++)
#pragma unroll
                for (int j = 0; j < 8; j++)
                    mma_f16(acc[t][j], ah[t], &bb[j >> 1][(j & 1) * 2]);
#pragma unroll
            for (int t = 0; t < 2; t++)
#pragma unroll
                for (int j = 0; j < 8; j++)
                    mma_f16(acc[t][j], al[t], &bb[j >> 1][(j & 1) * 2]);
        }
        __syncthreads();
    }

    // epilogue: c0 = gate_i, c1 = up_i (row-interleaved B) -> h = silu(g)*u
#pragma unroll
    for (int t = 0; t < 2; t++)
#pragma unroll
        for (int rh = 0; rh < 2; rh++) {
            int m = m0 + wm * 32 + t * 16 + rh * 8 + (lane >> 2);
            if (m < cnt) {
                size_t base = ((size_t)e * CAP + m) * IDIM + x0 * 64 + wn * 32 + (lane & 3);
#pragma unroll
                for (int j = 0; j < 8; j++) {
                    float gg = acc[t][j][rh * 2];
                    float uu = acc[t][j][rh * 2 + 1];
                    float hh = gg * (1.f / (1.f + expf(-gg))) * uu;
                    g_H[base + j * 4] = __float2half_rn(hh);
                }
            }
        }
}

// ---------------- GEMM phase 2: Y = H down^T, 1-pass fp16 mma.sync ---------
__global__ __launch_bounds__(THREADS)
void phase2_kernel() {
    extern __shared__ char smem[];
    const int e = blockIdx.z;
    const int cnt = min(g_counts[e], CAP);
    const int m0 = blockIdx.y * 128;
    if (m0 >= cnt) return;
    const int d0 = blockIdx.x * 128;
    const uint32_t sb = smem_u32(smem);

    const int tid = threadIdx.x;
    const int lane = tid & 31;
    const int wid = tid >> 5;
    const int wm = wid >> 1;
    const int wn = wid & 1;
    const int mycc = tid & 7;

    const size_t abase = ((size_t)e * CAP + m0) * IDIM;
    const size_t bbase = ((size_t)e * DDIM + d0) * IDIM;

    auto load_chunk = [&](int buf, int c) {
        uint32_t s = sb + buf * 2 * TILE_B;
        int kk = c * 64;
#pragma unroll
        for (int it = 0; it < 4; it++) {
            int row = (tid >> 3) + 32 * it;
            uint32_t dst = s + row * 128 + (((mycc ^ (row & 7))) << 4);
            size_t ka = abase + (size_t)row * IDIM + kk + mycc * 8;
            cp_async16(dst,          g_H + ka);
            size_t kb = bbase + (size_t)row * IDIM + kk + mycc * 8;
            cp_async16(dst + TILE_B, g_D + kb);
        }
    };

    float acc[2][8][4] = {};
    const int g = lane >> 3;
    const int ar_off = (lane & 7) + (g & 1) * 8;
    const int ac_off = g >> 1;
    const int br_off = (lane & 7) + (g >> 1) * 8;
    const int bc_off = g & 1;

    load_chunk(0, 0); CP_COMMIT();
    for (int c = 0; c < 8; c++) {
        if (c + 1 < 8) { load_chunk((c + 1) & 1, c + 1); CP_COMMIT(); CP_WAIT1(); }
        else CP_WAIT0();
        __syncthreads();
        uint32_t s = sb + (c & 1) * 2 * TILE_B;
#pragma unroll
        for (int h = 0; h < 4; h++) {
            uint32_t ah[2][4], bb[4][4];
#pragma unroll
            for (int t = 0; t < 2; t++) {
                int r = wm * 32 + t * 16 + ar_off;
                int cc = h * 2 + ac_off;
                ldsm4(ah[t], s + r * 128 + ((cc ^ (r & 7)) << 4));
            }
#pragma unroll
            for (int j2 = 0; j2 < 4; j2++) {
                int n = wn * 64 + j2 * 16 + br_off;
                int cc = h * 2 + bc_off;
                ldsm4(bb[j2], s + TILE_B + n * 128 + ((cc ^ (n & 7)) << 4));
            }
#pragma unroll
            for (int t = 0; t < 2; t++)
#pragma unroll
                for (int j = 0; j < 8; j++)
                    mma_f16(acc[t][j], ah[t], &bb[j >> 1][(j & 1) * 2]);
        }
        __syncthreads();
    }

#pragma unroll
    for (int t = 0; t < 2; t++)
#pragma unroll
        for (int rh = 0; rh < 2; rh++) {
            int m = m0 + wm * 32 + t * 16 + rh * 8 + (lane >> 2);
            if (m < cnt) {
                float* yp = &g_Y[((size_t)e * CAP + m) * DDIM + d0 + wn * 64 + (lane & 3) * 2];
#pragma unroll
                for (int j = 0; j < 8; j++) {
                    float2 v = make_float2(acc[t][j][rh * 2], acc[t][j][rh * 2 + 1]);
                    *(float2*)(yp + j * 8) = v;
                }
            }
        }
}

// ---------------- host ------------------------------------------------------
extern "C" void kernel_launch(void* const* d_in, const int* in_sizes, int n_in,
                              void* d_out, int out_size) {
    const float* x  = (const float*)d_in[0];
    const float* rw = (const float*)d_in[1];
    const float* gw = (const float*)d_in[2];
    const float* uw = (const float*)d_in[3];
    const float* dw = (const float*)d_in[4];
    float* out = (float*)d_out;
    float* logits = (out_size >= NTOK * DDIM + NTOK * NEXP) ? (out + (size_t)NTOK * DDIM)
                                                            : nullptr;

    cudaFuncSetAttribute(phase1_kernel, cudaFuncAttributeMaxDynamicSharedMemorySize, SMEM_P1);
    cudaFuncSetAttribute(phase2_kernel, cudaFuncAttributeMaxDynamicSharedMemorySize, SMEM_P2);

    zero_counts_kernel<<<1, 32>>>();
    router_kernel<<<NTOK, 128>>>(x, rw, logits);
    split_x_kernel<<<(NTOK * DDIM / 8 + 255) / 256, 256>>>(x);
    convert_gu_kernel<<<(NEXP * 1024 * DDIM / 8 + 255) / 256, 256>>>(gw, uw);
    convert_d_kernel<<<(NEXP * DDIM * IDIM / 8 + 255) / 256, 256>>>(dw);
    phase1_kernel<<<dim3(IDIM / 64, CAP / 128, NEXP), THREADS, SMEM_P1>>>();
    phase2_kernel<<<dim3(DDIM / 128, CAP / 128, NEXP), THREADS, SMEM_P2>>>();
    combine_kernel<<<NTOK, 256>>>(out);
}

// round 11
// speedup vs baseline: 4.0181x; 1.2690x over previous
#include <cuda_runtime.h>
#include <cuda_fp16.h>
#include <math.h>
#include <stdint.h>

#define NEXP 32
#define KSEL 4
#define CAP  1280
#define NTOK 8192
#define DDIM 1024
#define IDIM 512

#define THREADS 256
#define TILE_B   16384                 // 128 rows x 64 fp16 (128B)
#define SMEM_P1  (2 * 2 * TILE_B + 1024)
#define SMEM_P2  (2 * 2 * TILE_B + 1024)

// ---------------- scratch (device globals; no allocation allowed) ----------
__device__ int   g_counts[NEXP];
__device__ int   g_row_token[NEXP * CAP];
__device__ int   g_tok_exp[NTOK * KSEL];
__device__ int   g_tok_pos[NTOK * KSEL];
__device__ float g_tok_w[NTOK * KSEL];

__device__ __half g_X [(size_t)NTOK * DDIM];
__device__ __half g_GU[(size_t)NEXP * 1024 * DDIM];   // gate/up row-interleaved
__device__ __half g_D [(size_t)NEXP * DDIM * IDIM];
__device__ __half g_H [(size_t)NEXP * CAP * IDIM];
__device__ float g_Y[(size_t)NEXP * CAP * DDIM];

// ---------------- PTX helpers (base compute_103 target only) ---------------
__device__ __forceinline__ uint32_t smem_u32(const void* p) {
    uint32_t a;
    asm("{ .reg .u64 t; cvta.to.shared.u64 t, %1; cvt.u32.u64 %0, t; }"
        : "=r"(a) : "l"(p));
    return a;
}
__device__ __forceinline__ void cp_async16(uint32_t dst, const void* src) {
    asm volatile("cp.async.cg.shared.global [%0], [%1], 16;"
                 :: "r"(dst), "l"(src));
}
#define CP_COMMIT() asm volatile("cp.async.commit_group;" ::: "memory")
#define CP_WAIT1()  asm volatile("cp.async.wait_group 1;" ::: "memory")
#define CP_WAIT0()  asm volatile("cp.async.wait_group 0;" ::: "memory")

__device__ __forceinline__ void ldsm4(uint32_t* r, uint32_t a) {
    asm volatile("ldmatrix.sync.aligned.m8n8.x4.shared.b16 {%0,%1,%2,%3}, [%4];"
                 : "=r"(r[0]), "=r"(r[1]), "=r"(r[2]), "=r"(r[3]) : "r"(a));
}
__device__ __forceinline__ void mma_f16(float* c, const uint32_t* a,
                                        const uint32_t* b) {
    asm volatile(
        "mma.sync.aligned.m16n8k16.row.col.f32.f16.f16.f32 "
        "{%0,%1,%2,%3}, {%4,%5,%6,%7}, {%8,%9}, {%0,%1,%2,%3};"
        : "+f"(c[0]), "+f"(c[1]), "+f"(c[2]), "+f"(c[3])
        : "r"(a[0]), "r"(a[1]), "r"(a[2]), "r"(a[3]), "r"(b[0]), "r"(b[1]));
}

__device__ __forceinline__ uint32_t packh2(float a, float b) {
    __half2 h = __floats2half2_rn(a, b);
    return *reinterpret_cast<uint32_t*>(&h);
}

// ---------------- prep kernels ----------------------------------------------
__global__ void convert_x_kernel(const float* __restrict__ x) {
    size_t u = (size_t)blockIdx.x * blockDim.x + threadIdx.x;  // 8 floats/unit
    if (u >= (size_t)NTOK * DDIM / 8) return;
    const float4* src = (const float4*)x + u * 2;
    float4 v0 = src[0], v1 = src[1];
    ((uint4*)g_X)[u] = make_uint4(packh2(v0.x, v0.y), packh2(v0.z, v0.w),
                                  packh2(v1.x, v1.y), packh2(v1.z, v1.w));
}

// gate/up interleave: GU row r (0..1023): even -> gate[r>>1], odd -> up[r>>1]
__global__ void convert_gu_kernel(const float* __restrict__ gate_w,
                                  const float* __restrict__ up_w) {
    size_t u = (size_t)blockIdx.x * blockDim.x + threadIdx.x;
    if (u >= (size_t)NEXP * 1024 * DDIM / 8) return;
    size_t o = u * 8;
    size_t gr = o >> 10;
    int k = (int)(o & 1023);
    int e = (int)(gr >> 10);
    int r = (int)(gr & 1023);
    int i = r >> 1;
    const float* src = ((r & 1) ? up_w : gate_w) + ((size_t)e * IDIM + i) * DDIM + k;
    const float4* s4 = (const float4*)src;
    float4 v0 = s4[0], v1 = s4[1];
    ((uint4*)g_GU)[u] = make_uint4(packh2(v0.x, v0.y), packh2(v0.z, v0.w),
                                   packh2(v1.x, v1.y), packh2(v1.z, v1.w));
}

__global__ void convert_d_kernel(const float* __restrict__ down_w) {
    size_t u = (size_t)blockIdx.x * blockDim.x + threadIdx.x;
    if (u >= (size_t)NEXP * DDIM * IDIM / 8) return;
    const float4* s4 = (const float4*)down_w + u * 2;
    float4 v0 = s4[0], v1 = s4[1];
    ((uint4*)g_D)[u] = make_uint4(packh2(v0.x, v0.y), packh2(v0.z, v0.w),
                                  packh2(v1.x, v1.y), packh2(v1.z, v1.w));
}

// ---------------- router / combine ------------------------------------------
__global__ void zero_counts_kernel() {
    if (threadIdx.x < NEXP) g_counts[threadIdx.x] = 0;
}

__global__ void router_kernel(const float* __restrict__ x,
                              const float* __restrict__ rw,
                              float* __restrict__ logits_out) {
    __shared__ float xs[DDIM];
    __shared__ float lsh[NEXP];
    const int t = blockIdx.x;
    const int tid = threadIdx.x;

    const float4* xrow = (const float4*)(x + (size_t)t * DDIM);
    float4* xs4 = (float4*)xs;
    for (int i = tid; i < DDIM / 4; i += 128) xs4[i] = xrow[i];
    __syncthreads();

    const int e = tid >> 2;
    const int s = tid & 3;
    const float4* w4 = (const float4*)(rw + e * DDIM + s * 256);
    const float4* a4 = (const float4*)(xs + s * 256);
    float acc = 0.f;
#pragma unroll 16
    for (int j = 0; j < 64; j++) {
        float4 a = a4[j], b = w4[j];
        acc += a.x * b.x + a.y * b.y + a.z * b.z + a.w * b.w;
    }
    acc += __shfl_xor_sync(0xffffffffu, acc, 1);
    acc += __shfl_xor_sync(0xffffffffu, acc, 2);
    if (s == 0) lsh[e] = acc;
    __syncthreads();

    if (tid < 32) {
        float lv = lsh[tid];
        if (logits_out) logits_out[(size_t)t * NEXP + tid] = lv;

        float cur = lv;
        float selv[KSEL];
        int   seli[KSEL];
#pragma unroll
        for (int k = 0; k < KSEL; k++) {
            float v = cur;
            int idx = tid;
#pragma unroll
            for (int off = 16; off; off >>= 1) {
                float ov = __shfl_xor_sync(0xffffffffu, v, off);
                int   oi = __shfl_xor_sync(0xffffffffu, idx, off);
                if (ov > v || (ov == v && oi < idx)) { v = ov; idx = oi; }
            }
            selv[k] = v;
            seli[k] = idx;
            if (tid == idx) cur = -3.4e38f;
        }

        if (tid < KSEL) {
            float m = selv[0];
            float sum = 0.f;
#pragma unroll
            for (int k = 0; k < KSEL; k++) sum += expf(selv[k] - m);
            float w = expf(selv[tid] - m) / sum;
            int   ex = seli[tid];
            int p = atomicAdd(&g_counts[ex], 1);
            int o = t * KSEL + tid;
            g_tok_exp[o] = ex;
            g_tok_pos[o] = p;
            g_tok_w[o]   = w;
            if (p < CAP) g_row_token[ex * CAP + p] = t;
        }
    }
}

__global__ void combine_kernel(float* __restrict__ out) {
    const int t = blockIdx.x;
    const int d = threadIdx.x * 4;
    float4 acc = make_float4(0.f, 0.f, 0.f, 0.f);
#pragma unroll
    for (int k = 0; k < KSEL; k++) {
        int o = t * KSEL + k;
        int e = g_tok_exp[o];
        int p = g_tok_pos[o];
        float w = g_tok_w[o];
        if (p < CAP) {
            float4 v = *(const float4*)&g_Y[((size_t)e * CAP + p) * DDIM + d];
            acc.x += w * v.x; acc.y += w * v.y;
            acc.z += w * v.z; acc.w += w * v.w;
        }
    }
    *(float4*)&out[(size_t)t * DDIM + d] = acc;
}

// ---------------- GEMM phase 1: H = swiglu(X GU^T), 1-pass fp16 mma.sync ---
__global__ __launch_bounds__(THREADS)
void phase1_kernel() {
    extern __shared__ char smem[];
    const int e = blockIdx.z;
    const int cnt = min(g_counts[e], CAP);
    const int m0 = blockIdx.y * 128;
    if (m0 >= cnt) return;
    const int x0 = blockIdx.x;          // 64 i-values per tile
    const uint32_t sb = smem_u32(smem);
    int* tok_s = (int*)(smem + 2 * 2 * TILE_B);

    const int tid = threadIdx.x;
    const int lane = tid & 31;
    const int wid = tid >> 5;
    const int wm = wid >> 1;
    const int wn = wid & 1;

    if (tid < 128) {
        int m = m0 + tid;
        tok_s[tid] = (m < cnt) ? g_row_token[e * CAP + m] : 0;
    }
    __syncthreads();

    int mytok[4];
#pragma unroll
    for (int it = 0; it < 4; it++) mytok[it] = tok_s[(tid >> 3) + 32 * it];
    const int mycc = tid & 7;

    const size_t bbase = ((size_t)e * 1024 + x0 * 128) * DDIM;

    auto load_chunk = [&](int buf, int c) {
        uint32_t s = sb + buf * 2 * TILE_B;
        int kk = c * 64;
#pragma unroll
        for (int it = 0; it < 4; it++) {
            int row = (tid >> 3) + 32 * it;
            uint32_t dst = s + row * 128 + (((mycc ^ (row & 7))) << 4);
            size_t ka = (size_t)mytok[it] * DDIM + kk + mycc * 8;
            cp_async16(dst,          g_X + ka);
            size_t kb = bbase + (size_t)row * DDIM + kk + mycc * 8;
            cp_async16(dst + TILE_B, g_GU + kb);
        }
    };

    float acc[2][8][4] = {};
    const int g = lane >> 3;
    const int ar_off = (lane & 7) + (g & 1) * 8;
    const int ac_off = g >> 1;
    const int br_off = (lane & 7) + (g >> 1) * 8;
    const int bc_off = g & 1;

    load_chunk(0, 0); CP_COMMIT();
    for (int c = 0; c < 16; c++) {
        if (c + 1 < 16) { load_chunk((c + 1) & 1, c + 1); CP_COMMIT(); CP_WAIT1(); }
        else CP_WAIT0();
        __syncthreads();
        uint32_t s = sb + (c & 1) * 2 * TILE_B;
#pragma unroll
        for (int h = 0; h < 4; h++) {
            uint32_t ah[2][4], bb[4][4];
#pragma unroll
            for (int t = 0; t < 2; t++) {
                int r = wm * 32 + t * 16 + ar_off;
                int cc = h * 2 + ac_off;
                ldsm4(ah[t], s + r * 128 + ((cc ^ (r & 7)) << 4));
            }
#pragma unroll
            for (int j2 = 0; j2 < 4; j2++) {
                int n = wn * 64 + j2 * 16 + br_off;
                int cc = h * 2 + bc_off;
                ldsm4(bb[j2], s + TILE_B + n * 128 + ((cc ^ (n & 7)) << 4));
            }
#pragma unroll
            for (int t = 0; t < 2; t++)
#pragma unroll
                for (int j = 0; j < 8; j++)
                    mma_f16(acc[t][j], ah[t], &bb[j >> 1][(j & 1) * 2]);
        }
        __syncthreads();
    }

    // epilogue: c0 = gate_i, c1 = up_i (row-interleaved B) -> h = silu(g)*u
#pragma unroll
    for (int t = 0; t < 2; t++)
#pragma unroll
        for (int rh = 0; rh < 2; rh++) {
            int m = m0 + wm * 32 + t * 16 + rh * 8 + (lane >> 2);
            if (m < cnt) {
                size_t base = ((size_t)e * CAP + m) * IDIM + x0 * 64 + wn * 32 + (lane & 3);
#pragma unroll
                for (int j = 0; j < 8; j++) {
                    float gg = acc[t][j][rh * 2];
                    float uu = acc[t][j][rh * 2 + 1];
                    float hh = gg * (1.f / (1.f + expf(-gg))) * uu;
                    g_H[base + j * 4] = __float2half_rn(hh);
                }
            }
        }
}

// ---------------- GEMM phase 2: Y = H down^T, 1-pass fp16 mma.sync ---------
__global__ __launch_bounds__(THREADS)
void phase2_kernel() {
    extern __shared__ char smem[];
    const int e = blockIdx.z;
    const int cnt = min(g_counts[e], CAP);
    const int m0 = blockIdx.y * 128;
    if (m0 >= cnt) return;
    const int d0 = blockIdx.x * 128;
    const uint32_t sb = smem_u32(smem);

    const int tid = threadIdx.x;
    const int lane = tid & 31;
    const int wid = tid >> 5;
    const int wm = wid >> 1;
    const int wn = wid & 1;
    const int mycc = tid & 7;

    const size_t abase = ((size_t)e * CAP + m0) * IDIM;
    const size_t bbase = ((size_t)e * DDIM + d0) * IDIM;

    auto load_chunk = [&](int buf, int c) {
        uint32_t s = sb + buf * 2 * TILE_B;
        int kk = c * 64;
#pragma unroll
        for (int it = 0; it < 4; it++) {
            int row = (tid >> 3) + 32 * it;
            uint32_t dst = s + row * 128 + (((mycc ^ (row & 7))) << 4);
            size_t ka = abase + (size_t)row * IDIM + kk + mycc * 8;
            cp_async16(dst,          g_H + ka);
            size_t kb = bbase + (size_t)row * IDIM + kk + mycc * 8;
            cp_async16(dst + TILE_B, g_D + kb);
        }
    };

    float acc[2][8][4] = {};
    const int g = lane >> 3;
    const int ar_off = (lane & 7) + (g & 1) * 8;
    const int ac_off = g >> 1;
    const int br_off = (lane & 7) + (g >> 1) * 8;
    const int bc_off = g & 1;

    load_chunk(0, 0); CP_COMMIT();
    for (int c = 0; c < 8; c++) {
        if (c + 1 < 8) { load_chunk((c + 1) & 1, c + 1); CP_COMMIT(); CP_WAIT1(); }
        else CP_WAIT0();
        __syncthreads();
        uint32_t s = sb + (c & 1) * 2 * TILE_B;
#pragma unroll
        for (int h = 0; h < 4; h++) {
            uint32_t ah[2][4], bb[4][4];
#pragma unroll
            for (int t = 0; t < 2; t++) {
                int r = wm * 32 + t * 16 + ar_off;
                int cc = h * 2 + ac_off;
                ldsm4(ah[t], s + r * 128 + ((cc ^ (r & 7)) << 4));
            }
#pragma unroll
            for (int j2 = 0; j2 < 4; j2++) {
                int n = wn * 64 + j2 * 16 + br_off;
                int cc = h * 2 + bc_off;
                ldsm4(bb[j2], s + TILE_B + n * 128 + ((cc ^ (n & 7)) << 4));
            }
#pragma unroll
            for (int t = 0; t < 2; t++)
#pragma unroll
                for (int j = 0; j < 8; j++)
                    mma_f16(acc[t][j], ah[t], &bb[j >> 1][(j & 1) * 2]);
        }
        __syncthreads();
    }

#pragma unroll
    for (int t = 0; t < 2; t++)
#pragma unroll
        for (int rh = 0; rh < 2; rh++) {
            int m = m0 + wm * 32 + t * 16 + rh * 8 + (lane >> 2);
            if (m < cnt) {
                float* yp = &g_Y[((size_t)e * CAP + m) * DDIM + d0 + wn * 64 + (lane & 3) * 2];
#pragma unroll
                for (int j = 0; j < 8; j++) {
                    float2 v = make_float2(acc[t][j][rh * 2], acc[t][j][rh * 2 + 1]);
                    *(float2*)(yp + j * 8) = v;
                }
            }
        }
}

// ---------------- host ------------------------------------------------------
extern "C" void kernel_launch(void* const* d_in, const int* in_sizes, int n_in,
                              void* d_out, int out_size) {
    const float* x  = (const float*)d_in[0];
    const float* rw = (const float*)d_in[1];
    const float* gw = (const float*)d_in[2];
    const float* uw = (const float*)d_in[3];
    const float* dw = (const float*)d_in[4];
    float* out = (float*)d_out;
    float* logits = (out_size >= NTOK * DDIM + NTOK * NEXP) ? (out + (size_t)NTOK * DDIM)
                                                            : nullptr;

    cudaFuncSetAttribute(phase1_kernel, cudaFuncAttributeMaxDynamicSharedMemorySize, SMEM_P1);
    cudaFuncSetAttribute(phase2_kernel, cudaFuncAttributeMaxDynamicSharedMemorySize, SMEM_P2);

    zero_counts_kernel<<<1, 32>>>();
    router_kernel<<<NTOK, 128>>>(x, rw, logits);
    convert_x_kernel<<<(NTOK * DDIM / 8 + 255) / 256, 256>>>(x);
    convert_gu_kernel<<<(NEXP * 1024 * DDIM / 8 + 255) / 256, 256>>>(gw, uw);
    convert_d_kernel<<<(NEXP * DDIM * IDIM / 8 + 255) / 256, 256>>>(dw);
    phase1_kernel<<<dim3(IDIM / 64, CAP / 128, NEXP), THREADS, SMEM_P1>>>();
    phase2_kernel<<<dim3(DDIM / 128, CAP / 128, NEXP), THREADS, SMEM_P2>>>();
    combine_kernel<<<NTOK, 256>>>(out);
}